// round 11
// baseline (speedup 1.0000x reference)
#include <cuda_runtime.h>
#include <cuda_bf16.h>
#include <cstdint>

// HyperedgeMeanAggregator: out[h,:] = mean_{e: seg_ids[e]==h} embed_table[node_idx[e],:]
// seg_ids SORTED, indices int32 (JAX x64 off).
//
// Structure (best measured): memset -> entry-chunk gather+sum with red.v4
// atomic flushes (R5 loop, ~81us, ~90% of L2 gather cap) -> ILP-4 divide pass.

#define FEAT 128
#define FEAT4 (FEAT / 4)          // 32 float4 per row -> one warp covers a row
#define CHUNK 128                 // entries per warp
#define AGG_BLOCK 256             // 8 warps per block
#define MAX_H 65536

__device__ float g_counts[MAX_H];

__device__ __forceinline__ void red_v4(float* addr, float4 v) {
    asm volatile("red.global.add.v4.f32 [%0], {%1, %2, %3, %4};"
                 :: "l"(addr), "f"(v.x), "f"(v.y), "f"(v.z), "f"(v.w)
                 : "memory");
}

__global__ __launch_bounds__(AGG_BLOCK)
void agg_kernel(const float* __restrict__ table,
                const int* __restrict__ node_idx,
                const int* __restrict__ seg_ids,
                float* __restrict__ out,
                int E) {
    int gwarp = (blockIdx.x * blockDim.x + threadIdx.x) >> 5;
    int lane  = threadIdx.x & 31;

    int start = gwarp * CHUNK;
    if (start >= E) return;
    int end = start + CHUNK;
    if (end > E) end = E;

    const float4* t4 = reinterpret_cast<const float4*>(table);

    float4 acc = make_float4(0.f, 0.f, 0.f, 0.f);
    float  cnt = 0.f;
    int cur = __ldg(&seg_ids[start]);

#define PROC(S, V)                                                   \
    do {                                                             \
        if ((S) != cur) {                                            \
            red_v4(out + (long long)cur * FEAT + lane * 4, acc);     \
            if (lane == 0) atomicAdd(&g_counts[cur], cnt);           \
            acc = make_float4(0.f, 0.f, 0.f, 0.f);                   \
            cnt = 0.f;                                               \
            cur = (S);                                               \
        }                                                            \
        acc.x += (V).x; acc.y += (V).y;                              \
        acc.z += (V).z; acc.w += (V).w;                              \
        cnt += 1.f;                                                  \
    } while (0)

    int e = start;
    // start is a multiple of 128, so int4 loads are 16B-aligned.
    for (; e + 4 <= end; e += 4) {
        int4 s4 = *reinterpret_cast<const int4*>(&seg_ids[e]);   // uniform bcast
        int4 n4 = *reinterpret_cast<const int4*>(&node_idx[e]);  // uniform bcast
        // Issue all 4 row gathers before any consumption -> MLP=4.
        float4 v0 = __ldg(&t4[(long long)n4.x * FEAT4 + lane]);
        float4 v1 = __ldg(&t4[(long long)n4.y * FEAT4 + lane]);
        float4 v2 = __ldg(&t4[(long long)n4.z * FEAT4 + lane]);
        float4 v3 = __ldg(&t4[(long long)n4.w * FEAT4 + lane]);
        PROC(s4.x, v0);
        PROC(s4.y, v1);
        PROC(s4.z, v2);
        PROC(s4.w, v3);
    }
    for (; e < end; ++e) {   // generic tail (unused when E % 128 == 0)
        int s = __ldg(&seg_ids[e]);
        int n = __ldg(&node_idx[e]);
        float4 v = __ldg(&t4[(long long)n * FEAT4 + lane]);
        PROC(s, v);
    }
#undef PROC

    // Final flush.
    red_v4(out + (long long)cur * FEAT + lane * 4, acc);
    if (lane == 0) atomicAdd(&g_counts[cur], cnt);
}

// Divide pass with ILP=4: 8 threads per hyperedge row, each thread owns 4
// consecutive float4s. All 4 load->mul->store chains are independent.
__global__ __launch_bounds__(256)
void div_kernel(float* __restrict__ out, int H) {
    int i = blockIdx.x * blockDim.x + threadIdx.x;   // one thread = 4 float4
    if (i >= H * 8) return;
    int h = i >> 3;
    int q = (i & 7) * 4;                             // float4 offset within row

    float c = __ldg(&g_counts[h]);
    float inv = 1.f / fmaxf(c, 1.f);                 // empty seg: 0 * 1 = 0

    float4* o4 = reinterpret_cast<float4*>(out) + (unsigned)h * FEAT4 + q;
    float4 a = o4[0];
    float4 b = o4[1];
    float4 d = o4[2];
    float4 f = o4[3];
    a.x *= inv; a.y *= inv; a.z *= inv; a.w *= inv;
    b.x *= inv; b.y *= inv; b.z *= inv; b.w *= inv;
    d.x *= inv; d.y *= inv; d.z *= inv; d.w *= inv;
    f.x *= inv; f.y *= inv; f.z *= inv; f.w *= inv;
    o4[0] = a;
    o4[1] = b;
    o4[2] = d;
    o4[3] = f;
}

extern "C" void kernel_launch(void* const* d_in, const int* in_sizes, int n_in,
                              void* d_out, int out_size) {
    const float* table    = (const float*)d_in[0];
    const int*   node_idx = (const int*)d_in[1];
    const int*   seg_ids  = (const int*)d_in[2];
    float*       out      = (float*)d_out;

    int E = in_sizes[1];
    int H = out_size / FEAT;

    // 1) zero output + counts (atomics need zero base)
    cudaMemsetAsync(out, 0, (size_t)out_size * sizeof(float));
    void* counts_ptr = nullptr;
    cudaGetSymbolAddress(&counts_ptr, g_counts);
    cudaMemsetAsync(counts_ptr, 0, (size_t)H * sizeof(float));

    // 2) gather + segment-sum accumulate
    {
        int warps = (E + CHUNK - 1) / CHUNK;
        int blocks = (warps * 32 + AGG_BLOCK - 1) / AGG_BLOCK;
        agg_kernel<<<blocks, AGG_BLOCK>>>(table, node_idx, seg_ids, out, E);
    }
    // 3) divide by counts -> mean
    {
        int total = H * 8;
        div_kernel<<<(total + 255) / 256, 256>>>(out, H);
    }
}